// round 15
// baseline (speedup 1.0000x reference)
#include <cuda_runtime.h>
#include <cuda_bf16.h>
#include <mma.h>
#include <cstdint>

using namespace nvcuda;

// Dims: B=32, S=64, T=63, L=64, U=512, E=256, V=32000
#define NB 32
#define NT 63
#define NL 64
#define NU 512
#define NE 256
#define NV 32000
#define G4 2048
#define RBLK 256

// ---------------- scratch (device globals) ------------------------------------
__device__ float g_x[2016 * 256];            // gathered embeddings, row = t*32+b
__device__ float g_xwx[2016 * 2048];         // x @ W_x, row = t*32+b
__device__ float g_encproj[2048 * 512];      // enc @ Wa, row = b*64+l
__device__ float g_h[NU * NB];               // TRANSPOSED: [u][b]
__device__ float g_hall[2016 * 512];         // [(b*63+t)][u]
__device__ float g_zpart[16 * G4 * NB];      // partials [s][col][b] (b contiguous)
__device__ float g_attnw[2016 * 64];         // softmax weights [(b*63+t)][l]
__device__ __align__(16) __nv_bfloat16 g_catb[2048 * 1024];   // [ctx|h] bf16, row = b*63+t
__device__ __align__(16) __nv_bfloat16 g_wfcb[1024 * 32000];  // W_fc bf16 [k][n]
__device__ float g_rowsum[2048];
__device__ unsigned g_barc, g_barr;

// ---------------- helpers ------------------------------------------------------
__device__ __forceinline__ uint32_t smem_u32(const void* p) {
    uint32_t a;
    asm("{ .reg .u64 t; cvta.to.shared.u64 t, %1; cvt.u32.u64 %0, t; }" : "=r"(a) : "l"(p));
    return a;
}
__device__ __forceinline__ void cp16(uint32_t dst, const void* src) {
    asm volatile("cp.async.cg.shared.global [%0], [%1], 16;" :: "r"(dst), "l"(src));
}
#define CP_COMMIT() asm volatile("cp.async.commit_group;" ::: "memory")
#define CP_WAIT(n)  asm volatile("cp.async.wait_group %0;" :: "n"(n) : "memory")

// ---------------- grid-wide barrier: release/acquire, no membar ---------------
__device__ __forceinline__ void gridbar(unsigned target) {
    __syncthreads();
    if (threadIdx.x == 0) {
        unsigned* pc;
        unsigned* pr;
        asm("cvta.global.u64 %0, %1;" : "=l"(pc) : "l"(&g_barc));
        asm("cvta.global.u64 %0, %1;" : "=l"(pr) : "l"(&g_barr));
        unsigned ticket;
        asm volatile("atom.add.acq_rel.gpu.u32 %0, [%1], 1;"
                     : "=r"(ticket) : "l"(pc) : "memory");
        if (ticket == target * RBLK - 1u) {
            asm volatile("st.release.gpu.u32 [%0], %1;" :: "l"(pr), "r"(target) : "memory");
        } else {
            unsigned v;
            do {
                asm volatile("ld.acquire.gpu.u32 %0, [%1];" : "=r"(v) : "l"(pr) : "memory");
            } while (v < target);
        }
    }
    __syncthreads();
}

// ---------------- conversions -------------------------------------------------
__global__ void convert_wfc_kernel(const float* __restrict__ wfc) {
    int i = (blockIdx.x * blockDim.x + threadIdx.x) * 4;
    int stride = gridDim.x * blockDim.x * 4;
    for (; i < 1024 * 32000; i += stride) {
        float4 v = *reinterpret_cast<const float4*>(wfc + i);
        g_wfcb[i + 0] = __float2bfloat16(v.x);
        g_wfcb[i + 1] = __float2bfloat16(v.y);
        g_wfcb[i + 2] = __float2bfloat16(v.z);
        g_wfcb[i + 3] = __float2bfloat16(v.w);
    }
}

// ---------------- embedding gather --------------------------------------------
__global__ void gather_x_kernel(const int* __restrict__ target,
                                const float* __restrict__ emb) {
    int r = blockIdx.x;          // r = t*32 + b
    int t = r >> 5;
    int b = r & 31;
    int tok = target[b * 64 + t];
    g_x[(size_t)r * NE + threadIdx.x] = emb[(size_t)tok * NE + threadIdx.x];
}

// ---------------- fp32 SGEMM, 128x64 tile, 8x4 per thread ---------------------
__global__ __launch_bounds__(256) void sgemm128(const float* __restrict__ A,
                                                const float* __restrict__ B,
                                                float* __restrict__ C,
                                                int M, int N, int K) {
    __shared__ float As[128 * 16];
    __shared__ float Bs[16 * 64];
    int tid = threadIdx.x;
    int m0 = blockIdx.y * 128, n0 = blockIdx.x * 64;
    int ty = tid >> 4, tx = tid & 15;
    int arow = tid >> 1, acol = (tid & 1) * 8;
    int brow = tid >> 4, bcol = (tid & 15) * 4;
    float acc[8][4] = {};
    for (int kt = 0; kt < K; kt += 16) {
        float4 a0 = make_float4(0.f, 0.f, 0.f, 0.f);
        float4 a1 = make_float4(0.f, 0.f, 0.f, 0.f);
        if (m0 + arow < M) {
            a0 = *reinterpret_cast<const float4*>(A + (size_t)(m0 + arow) * K + kt + acol);
            a1 = *reinterpret_cast<const float4*>(A + (size_t)(m0 + arow) * K + kt + acol + 4);
        }
        *reinterpret_cast<float4*>(&As[arow * 16 + acol]) = a0;
        *reinterpret_cast<float4*>(&As[arow * 16 + acol + 4]) = a1;
        *reinterpret_cast<float4*>(&Bs[brow * 64 + bcol]) =
            *reinterpret_cast<const float4*>(B + (size_t)(kt + brow) * N + n0 + bcol);
        __syncthreads();
#pragma unroll
        for (int k = 0; k < 16; k++) {
            float4 b4 = *reinterpret_cast<float4*>(&Bs[k * 64 + tx * 4]);
#pragma unroll
            for (int i = 0; i < 8; i++) {
                float a = As[(ty * 8 + i) * 16 + k];
                acc[i][0] += a * b4.x; acc[i][1] += a * b4.y;
                acc[i][2] += a * b4.z; acc[i][3] += a * b4.w;
            }
        }
        __syncthreads();
    }
#pragma unroll
    for (int i = 0; i < 8; i++) {
        int r = m0 + ty * 8 + i;
        if (r < M)
            *reinterpret_cast<float4*>(C + (size_t)r * N + n0 + tx * 4) =
                make_float4(acc[i][0], acc[i][1], acc[i][2], acc[i][3]);
    }
}

// ---------------- init: transposed h, counters, rowsum ------------------------
__global__ void init_kernel(const float* __restrict__ h0) {
    int idx = blockIdx.x * blockDim.x + threadIdx.x;   // 16384 threads
    int b = idx >> 9, u = idx & 511;
    g_h[u * 32 + b] = h0[idx];
    if (idx < 2048) g_rowsum[idx] = 0.f;
    if (idx == 0) { g_barc = 0; g_barr = 0; }
}

// ---------------- persistent recurrence v2: f32x2 FMA, regs for Wh ------------
// 256 blocks x 128 threads, 2/SM. cg = bid>>4 (128 cols), ks = bid&15 (32 k).
// Gates role (blocks 0..127): thread <-> (b,u), c in register.
__global__ __launch_bounds__(128, 2) void recur_kernel(
        const float* __restrict__ Wh,
        const float* __restrict__ b_lstm,
        const float* __restrict__ c0) {
    __shared__ float hs[1024];           // h slice [k 32][b 32]
    int bid = blockIdx.x, tid = threadIdx.x;
    int cg = bid >> 4, ks = bid & 15;
    int col = cg * 128 + tid;
    int k0 = ks * 32;

    // preload Wh slice into registers: 32 k-values for this column
    float wreg[32];
#pragma unroll
    for (int k = 0; k < 32; k++)
        wreg[k] = __ldg(&Wh[(size_t)(k0 + k) * G4 + col]);

    int gb = 0, gu = 0;
    float c = 0.f, bl0 = 0.f, bl1 = 0.f, bl2 = 0.f, bl3 = 0.f;
    if (bid < 128) {
        int gidx = bid * 128 + tid;
        gb = gidx >> 9; gu = gidx & 511;
        c = c0[gb * 512 + gu];
        bl0 = b_lstm[gu];        bl1 = b_lstm[512 + gu];
        bl2 = b_lstm[1024 + gu]; bl3 = b_lstm[1536 + gu];
    }

    float* zcol = &g_zpart[((size_t)ks * G4 + col) * NB];   // 32 b-contiguous

    for (int t = 0; t < NT; t++) {
        // stage h slice (written by gates last step; L2-coherent, bypass L1)
#pragma unroll
        for (int i = 0; i < 2; i++) {
            float4 v = __ldcg(reinterpret_cast<const float4*>(
                &g_h[k0 * 32 + tid * 4 + i * 512]));
            *reinterpret_cast<float4*>(&hs[tid * 4 + i * 512]) = v;
        }
        __syncthreads();

        // packed-f32x2 GEMM: acc[b-pair] += h[b-pair] * (w,w)
        unsigned long long accp[16] = {};
#pragma unroll 4
        for (int k = 0; k < 32; k++) {
            unsigned long long wp;
            asm("mov.b64 %0, {%1, %1};" : "=l"(wp) : "f"(wreg[k]));
            const ulonglong2* hp = reinterpret_cast<const ulonglong2*>(&hs[k * 32]);
#pragma unroll
            for (int q = 0; q < 8; q++) {
                ulonglong2 h2 = hp[q];
                asm("fma.rn.f32x2 %0, %1, %2, %0;"
                    : "+l"(accp[q * 2 + 0]) : "l"(h2.x), "l"(wp));
                asm("fma.rn.f32x2 %0, %1, %2, %0;"
                    : "+l"(accp[q * 2 + 1]) : "l"(h2.y), "l"(wp));
            }
        }
#pragma unroll
        for (int p = 0; p < 16; p++)
            *reinterpret_cast<unsigned long long*>(&zcol[p * 2]) = accp[p];

        gridbar(2 * t + 1);

        if (bid < 128) {
            const float* xw = g_xwx + (size_t)(t * 32 + gb) * G4;
            float zi = __ldg(xw + gu)        + bl0;
            float zf = __ldg(xw + 512 + gu)  + bl1;
            float zg = __ldg(xw + 1024 + gu) + bl2;
            float zo = __ldg(xw + 1536 + gu) + bl3;
#pragma unroll
            for (int s = 0; s < 16; s++) {
                const float* zp = g_zpart + (size_t)s * G4 * NB + gb;
                zi += __ldcg(zp + (size_t)gu * NB);
                zf += __ldcg(zp + (size_t)(512 + gu) * NB);
                zg += __ldcg(zp + (size_t)(1024 + gu) * NB);
                zo += __ldcg(zp + (size_t)(1536 + gu) * NB);
            }
            float ig = 1.f / (1.f + expf(-zi));
            float fg = 1.f / (1.f + expf(-zf));
            float gg = tanhf(zg);
            float og = 1.f / (1.f + expf(-zo));
            c = fg * c + ig * gg;
            float h = og * tanhf(c);
            g_h[gu * 32 + gb] = h;
            g_hall[(size_t)(gb * 63 + t) * 512 + gu] = h;
            g_catb[(size_t)(gb * 63 + t) * 1024 + 512 + gu] = __float2bfloat16(h);
        }

        gridbar(2 * t + 2);
    }
}

// ---------------- batched attention: scores + softmax -------------------------
__global__ __launch_bounds__(256) void score_kernel() {
    int b = blockIdx.x, th = blockIdx.y;
    int t0 = th * 32;
    int nt = th ? 31 : 32;
    __shared__ float se[64 * 65];
    __shared__ float sh[32 * 65];
    int tid = threadIdx.x;
    int tq = tid >> 5, lq = tid & 31;
    float a[4][2] = {};
    for (int kc = 0; kc < 8; kc++) {
        int kk0 = kc * 64;
        for (int i = tid; i < 64 * 64; i += 256) {
            int l = i >> 6, kk = i & 63;
            se[l * 65 + kk] = g_encproj[((size_t)b * 64 + l) * 512 + kk0 + kk];
        }
        for (int i = tid; i < 32 * 64; i += 256) {
            int tt = i >> 6, kk = i & 63;
            sh[tt * 65 + kk] = (tt < nt)
                ? g_hall[((size_t)(b * 63 + t0 + tt)) * 512 + kk0 + kk] : 0.f;
        }
        __syncthreads();
#pragma unroll 8
        for (int kk = 0; kk < 64; kk++) {
            float e0 = se[lq * 65 + kk];
            float e1 = se[(lq + 32) * 65 + kk];
#pragma unroll
            for (int ii = 0; ii < 4; ii++) {
                float hv = sh[(tq * 4 + ii) * 65 + kk];
                a[ii][0] += hv * e0;
                a[ii][1] += hv * e1;
            }
        }
        __syncthreads();
    }
#pragma unroll
    for (int ii = 0; ii < 4; ii++) {
        float m = fmaxf(a[ii][0], a[ii][1]);
        for (int off = 16; off; off >>= 1)
            m = fmaxf(m, __shfl_xor_sync(0xffffffffu, m, off));
        float e0 = expf(a[ii][0] - m), e1 = expf(a[ii][1] - m);
        float s = e0 + e1;
        for (int off = 16; off; off >>= 1)
            s += __shfl_xor_sync(0xffffffffu, s, off);
        int tt = tq * 4 + ii;
        if (tt < nt) {
            size_t base = (size_t)(b * 63 + t0 + tt) * 64;
            g_attnw[base + lq]      = e0 / s;
            g_attnw[base + lq + 32] = e1 / s;
        }
    }
}

// ---------------- batched ctx = attn @ enc, write bf16 directly ---------------
__global__ __launch_bounds__(512) void ctx_kernel(const float* __restrict__ enc) {
    int b = blockIdx.x, tg = blockIdx.y;
    int u = threadIdx.x;
    __shared__ float aw[9 * 64];
    for (int i = u; i < 9 * 64; i += 512) {
        int tt = i >> 6, l = i & 63;
        aw[i] = g_attnw[(size_t)(b * 63 + tg * 9 + tt) * 64 + l];
    }
    __syncthreads();
    float acc[9] = {};
#pragma unroll 4
    for (int l = 0; l < 64; l++) {
        float e = __ldg(&enc[((size_t)b * 64 + l) * 512 + u]);
#pragma unroll
        for (int tt = 0; tt < 9; tt++) acc[tt] += aw[tt * 64 + l] * e;
    }
#pragma unroll
    for (int tt = 0; tt < 9; tt++)
        g_catb[(size_t)(b * 63 + tg * 9 + tt) * 1024 + u] = __float2bfloat16(acc[tt]);
}

// ---------------- output FC v2: 128x256 block, 64x64 warp tiles ---------------
#define FC_ALD 40
#define FC_BLD 280
#define FC_SMEM 56832

__global__ __launch_bounds__(256) void fc_wmma_kernel(const float* __restrict__ b_fc,
                                                      float* __restrict__ out) {
    extern __shared__ char smem[];
    __nv_bfloat16* Asp = reinterpret_cast<__nv_bfloat16*>(smem);
    __nv_bfloat16* Bsp = reinterpret_cast<__nv_bfloat16*>(smem + 20480);
    float* rowacc = reinterpret_cast<float*>(smem + 56320);
    float* stageb = reinterpret_cast<float*>(smem);

    int tid = threadIdx.x;
    int n0 = blockIdx.x * 256, m0 = blockIdx.y * 128;
    int w = tid >> 5, lane = tid & 31;
    int warpM = w >> 2, warpN = w & 3;           // 2 x 4 warps, warp tile 64x64

    uint32_t asu = smem_u32(Asp);
    uint32_t bsu = smem_u32(Bsp);

    auto load_tile = [&](int buf, int ktc) {
        uint32_t ab = asu + (uint32_t)buf * 10240;
        uint32_t bb = bsu + (uint32_t)buf * 17920;
#pragma unroll
        for (int rep = 0; rep < 2; rep++) {
            int o = tid + rep * 256;
            int row = o >> 2, c8 = (o & 3) * 8;
            cp16(ab + (uint32_t)(row * FC_ALD + c8) * 2,
                 g_catb + ((size_t)(m0 + row) * 1024 + ktc * 32 + c8));
        }
#pragma unroll
        for (int rep = 0; rep < 4; rep++) {
            int o = tid + rep * 256;
            int row2 = o >> 5, seg = (o & 31) * 8;
            cp16(bb + (uint32_t)(row2 * FC_BLD + seg) * 2,
                 g_wfcb + ((size_t)(ktc * 32 + row2) * 32000 + n0 + seg));
        }
        CP_COMMIT();
    };

    wmma::fragment<wmma::accumulator, 16, 16, 16, float> acc[4][4];
#pragma unroll
    for (int mi = 0; mi < 4; mi++)
#pragma unroll
        for (int ni = 0; ni < 4; ni++) wmma::fill_fragment(acc[mi][ni], 0.f);

    load_tile(0, 0);

    for (int kt = 0; kt < 32; kt++) {
        int cur = kt & 1;
        if (kt + 1 < 32) {
            load_tile(cur ^ 1, kt + 1);
            CP_WAIT(1);
        } else {
            CP_WAIT(0);
        }
        __syncthreads();

        const __nv_bfloat16* Ab = Asp + cur * 5120;
        const __nv_bfloat16* Bb = Bsp + cur * 8960;
#pragma unroll
        for (int kf = 0; kf < 2; kf++) {
            wmma::fragment<wmma::matrix_a, 16, 16, 16, __nv_bfloat16, wmma::row_major> af[4];
            wmma::fragment<wmma::matrix_b, 16, 16, 16, __nv_bfloat16, wmma::row_major> bfr[4];
#pragma unroll
            for (int mi = 0; mi < 4; mi++)
                wmma::load_matrix_sync(af[mi], Ab + (warpM * 64 + mi * 16) * FC_ALD + kf * 16, FC_ALD);
#pragma unroll
            for (int ni = 0; ni < 4; ni++)
                wmma::load_matrix_sync(bfr[ni], Bb + (kf * 16) * FC_BLD + warpN * 64 + ni * 16, FC_BLD);
#pragma unroll
            for (int mi = 0; mi < 4; mi++)
#pragma unroll
                for (int ni = 0; ni < 4; ni++)
                    wmma::mma_sync(acc[mi][ni], af[mi], bfr[ni], acc[mi][ni]);
        }
        __syncthreads();
    }

    // epilogue: stage in As[0] region, rowacc for exp sums
    if (tid < 128) rowacc[tid] = 0.f;
    __syncthreads();

    float* st = stageb + w * 256;
#pragma unroll
    for (int mi = 0; mi < 4; mi++) {
#pragma unroll
        for (int ni = 0; ni < 4; ni++) {
            wmma::store_matrix_sync(st, acc[mi][ni], 16, wmma::mem_row_major);
            __syncwarp();
            int r0 = m0 + warpM * 64 + mi * 16;
            int c0 = n0 + warpN * 64 + ni * 16;
#pragma unroll
            for (int j = 0; j < 8; j++) {
                int e = lane + j * 32;
                int rr = e >> 4, cc = e & 15;
                int r = r0 + rr;
                float val = tanhf(st[e] + __ldg(&b_fc[c0 + cc]));
                if (r < 2016)
                    out[(size_t)r * 32000 + c0 + cc] = val;
                // exp row-sum: |val| <= 1, no max-stabilization needed.
                float ex = __expf(val);
                ex += __shfl_xor_sync(0xffffffffu, ex, 8);
                ex += __shfl_xor_sync(0xffffffffu, ex, 4);
                ex += __shfl_xor_sync(0xffffffffu, ex, 2);
                ex += __shfl_xor_sync(0xffffffffu, ex, 1);
                if ((lane & 15) == 0)
                    atomicAdd(&rowacc[warpM * 64 + mi * 16 + rr], ex);
            }
            __syncwarp();
        }
    }
    __syncthreads();
    if (tid < 128) {
        int r = m0 + tid;
        if (r < 2016) atomicAdd(&g_rowsum[r], rowacc[tid]);
    }
}

// ---------------- subtract log(rowsum) ----------------------------------------
__global__ void sub_kernel(float* __restrict__ out) {
    int r = blockIdx.y;
    int v = (blockIdx.x * 256 + threadIdx.x) * 4;
    if (v < NV) {
        float lg = logf(g_rowsum[r]);
        float4* p = reinterpret_cast<float4*>(out + (size_t)r * NV + v);
        float4 x = *p;
        x.x -= lg; x.y -= lg; x.z -= lg; x.w -= lg;
        *p = x;
    }
}

// ---------------- launch ------------------------------------------------------
extern "C" void kernel_launch(void* const* d_in, const int* in_sizes, int n_in,
                              void* d_out, int out_size) {
    const int*   target = (const int*)d_in[0];
    const float* enc    = (const float*)d_in[1];
    const float* h0     = (const float*)d_in[2];
    const float* c0     = (const float*)d_in[3];
    const float* emb    = (const float*)d_in[4];
    const float* W_x    = (const float*)d_in[5];
    const float* W_h    = (const float*)d_in[6];
    const float* b_lstm = (const float*)d_in[7];
    const float* Wa     = (const float*)d_in[8];
    const float* W_fc   = (const float*)d_in[9];
    const float* b_fc   = (const float*)d_in[10];
    float* out = (float*)d_out;

    float *px, *pxwx, *pencproj;
    cudaGetSymbolAddress((void**)&px, g_x);
    cudaGetSymbolAddress((void**)&pxwx, g_xwx);
    cudaGetSymbolAddress((void**)&pencproj, g_encproj);

    cudaFuncSetAttribute(fc_wmma_kernel, cudaFuncAttributeMaxDynamicSharedMemorySize, FC_SMEM);

    // ordered so recur_kernel is the 4th launch (gets the ncu sample)
    gather_x_kernel<<<2016, 256>>>(target, emb);
    // xWx = g_x(2016x256) @ W_x(256x2048)
    sgemm128<<<dim3(32, 16), 256>>>(px, W_x, pxwx, 2016, 2048, 256);
    init_kernel<<<64, 256>>>(h0);
    // fused 63-step recurrence (persistent, grid-wide barriers)
    recur_kernel<<<RBLK, 128>>>(W_h, b_lstm, c0);

    // encproj = enc(2048x512) @ Wa(512x512)  (needed only by score)
    sgemm128<<<dim3(8, 16), 256>>>(enc, Wa, pencproj, 2048, 512, 512);
    score_kernel<<<dim3(32, 2), 256>>>();
    ctx_kernel<<<dim3(32, 7), 512>>>(enc);

    convert_wfc_kernel<<<4096, 256>>>(W_fc);
    // big FC with fused exp-rowsum, then log-softmax finalize
    fc_wmma_kernel<<<dim3(125, 16), 256, FC_SMEM>>>(b_fc, out);
    sub_kernel<<<dim3(32, 2016), 256>>>(out);
}

// round 16
// speedup vs baseline: 1.2185x; 1.2185x over previous
#include <cuda_runtime.h>
#include <cuda_bf16.h>
#include <mma.h>
#include <cstdint>

using namespace nvcuda;

// Dims: B=32, S=64, T=63, L=64, U=512, E=256, V=32000
#define NB 32
#define NT 63
#define NL 64
#define NU 512
#define NE 256
#define NV 32000
#define G4 2048
#define RBLK 256

// ---------------- scratch (device globals) ------------------------------------
__device__ float g_x[2016 * 256];            // gathered embeddings, row = t*32+b
__device__ float g_xwx[2016 * 2048];         // x @ W_x, row = t*32+b
__device__ float g_encproj[2048 * 512];      // enc @ Wa, row = b*64+l
__device__ float g_h[NU * NB];               // TRANSPOSED: [u][b]
__device__ float g_hall[2016 * 512];         // [(b*63+t)][u]
__device__ float g_zpart[16 * NB * G4];      // partials [ks*32+b][col]  (coalesced)
__device__ float g_attnw[2016 * 64];         // softmax weights [(b*63+t)][l]
__device__ __align__(16) __nv_bfloat16 g_catb[2048 * 1024];   // [ctx|h] bf16, row = b*63+t
__device__ __align__(16) __nv_bfloat16 g_wfcb[1024 * 32000];  // W_fc bf16 [k][n]
__device__ float g_rowsum[2048];
__device__ unsigned g_barc, g_barr;

// ---------------- helpers ------------------------------------------------------
__device__ __forceinline__ uint32_t smem_u32(const void* p) {
    uint32_t a;
    asm("{ .reg .u64 t; cvta.to.shared.u64 t, %1; cvt.u32.u64 %0, t; }" : "=r"(a) : "l"(p));
    return a;
}
__device__ __forceinline__ void cp16(uint32_t dst, const void* src) {
    asm volatile("cp.async.cg.shared.global [%0], [%1], 16;" :: "r"(dst), "l"(src));
}
#define CP_COMMIT() asm volatile("cp.async.commit_group;" ::: "memory")
#define CP_WAIT(n)  asm volatile("cp.async.wait_group %0;" :: "n"(n) : "memory")

// ---------------- grid-wide barrier: release/acquire --------------------------
__device__ __forceinline__ void gridbar(unsigned target) {
    __syncthreads();
    if (threadIdx.x == 0) {
        unsigned* pc;
        unsigned* pr;
        asm("cvta.global.u64 %0, %1;" : "=l"(pc) : "l"(&g_barc));
        asm("cvta.global.u64 %0, %1;" : "=l"(pr) : "l"(&g_barr));
        unsigned ticket;
        asm volatile("atom.add.acq_rel.gpu.u32 %0, [%1], 1;"
                     : "=r"(ticket) : "l"(pc) : "memory");
        if (ticket == target * RBLK - 1u) {
            asm volatile("st.release.gpu.u32 [%0], %1;" :: "l"(pr), "r"(target) : "memory");
        } else {
            unsigned v;
            do {
                asm volatile("ld.acquire.gpu.u32 %0, [%1];" : "=r"(v) : "l"(pr) : "memory");
            } while (v < target);
        }
    }
    __syncthreads();
}

// ---------------- conversions -------------------------------------------------
__global__ void convert_wfc_kernel(const float* __restrict__ wfc) {
    int i = (blockIdx.x * blockDim.x + threadIdx.x) * 4;
    int stride = gridDim.x * blockDim.x * 4;
    for (; i < 1024 * 32000; i += stride) {
        float4 v = *reinterpret_cast<const float4*>(wfc + i);
        g_wfcb[i + 0] = __float2bfloat16(v.x);
        g_wfcb[i + 1] = __float2bfloat16(v.y);
        g_wfcb[i + 2] = __float2bfloat16(v.z);
        g_wfcb[i + 3] = __float2bfloat16(v.w);
    }
}

// ---------------- embedding gather --------------------------------------------
__global__ void gather_x_kernel(const int* __restrict__ target,
                                const float* __restrict__ emb) {
    int r = blockIdx.x;          // r = t*32 + b
    int t = r >> 5;
    int b = r & 31;
    int tok = target[b * 64 + t];
    g_x[(size_t)r * NE + threadIdx.x] = emb[(size_t)tok * NE + threadIdx.x];
}

// ---------------- fp32 SGEMM, 128x64 tile, 8x4 per thread ---------------------
__global__ __launch_bounds__(256) void sgemm128(const float* __restrict__ A,
                                                const float* __restrict__ B,
                                                float* __restrict__ C,
                                                int M, int N, int K) {
    __shared__ float As[128 * 16];
    __shared__ float Bs[16 * 64];
    int tid = threadIdx.x;
    int m0 = blockIdx.y * 128, n0 = blockIdx.x * 64;
    int ty = tid >> 4, tx = tid & 15;
    int arow = tid >> 1, acol = (tid & 1) * 8;
    int brow = tid >> 4, bcol = (tid & 15) * 4;
    float acc[8][4] = {};
    for (int kt = 0; kt < K; kt += 16) {
        float4 a0 = make_float4(0.f, 0.f, 0.f, 0.f);
        float4 a1 = make_float4(0.f, 0.f, 0.f, 0.f);
        if (m0 + arow < M) {
            a0 = *reinterpret_cast<const float4*>(A + (size_t)(m0 + arow) * K + kt + acol);
            a1 = *reinterpret_cast<const float4*>(A + (size_t)(m0 + arow) * K + kt + acol + 4);
        }
        *reinterpret_cast<float4*>(&As[arow * 16 + acol]) = a0;
        *reinterpret_cast<float4*>(&As[arow * 16 + acol + 4]) = a1;
        *reinterpret_cast<float4*>(&Bs[brow * 64 + bcol]) =
            *reinterpret_cast<const float4*>(B + (size_t)(kt + brow) * N + n0 + bcol);
        __syncthreads();
#pragma unroll
        for (int k = 0; k < 16; k++) {
            float4 b4 = *reinterpret_cast<float4*>(&Bs[k * 64 + tx * 4]);
#pragma unroll
            for (int i = 0; i < 8; i++) {
                float a = As[(ty * 8 + i) * 16 + k];
                acc[i][0] += a * b4.x; acc[i][1] += a * b4.y;
                acc[i][2] += a * b4.z; acc[i][3] += a * b4.w;
            }
        }
        __syncthreads();
    }
#pragma unroll
    for (int i = 0; i < 8; i++) {
        int r = m0 + ty * 8 + i;
        if (r < M)
            *reinterpret_cast<float4*>(C + (size_t)r * N + n0 + tx * 4) =
                make_float4(acc[i][0], acc[i][1], acc[i][2], acc[i][3]);
    }
}

// ---------------- init: transposed h, counters, rowsum ------------------------
__global__ void init_kernel(const float* __restrict__ h0) {
    int idx = blockIdx.x * blockDim.x + threadIdx.x;   // 16384 threads
    int b = idx >> 9, u = idx & 511;
    g_h[u * 32 + b] = h0[idx];
    if (idx < 2048) g_rowsum[idx] = 0.f;
    if (idx == 0) { g_barc = 0; g_barr = 0; }
}

// ---------------- persistent recurrence v3: f32x2 FMA, coalesced zpart --------
// 256 blocks x 128 threads, 2/SM. cg = bid>>4 (128 cols), ks = bid&15 (32 k).
// Gates role (blocks 0..127): thread <-> (b,u), c in register.
__global__ __launch_bounds__(128, 2) void recur_kernel(
        const float* __restrict__ Wh,
        const float* __restrict__ b_lstm,
        const float* __restrict__ c0) {
    __shared__ float hs[1024];           // h slice [k 32][b 32]
    int bid = blockIdx.x, tid = threadIdx.x;
    int cg = bid >> 4, ks = bid & 15;
    int col = cg * 128 + tid;
    int k0 = ks * 32;

    // preload Wh slice into registers: 32 k-values for this column
    float wreg[32];
#pragma unroll
    for (int k = 0; k < 32; k++)
        wreg[k] = __ldg(&Wh[(size_t)(k0 + k) * G4 + col]);

    int gb = 0, gu = 0;
    float c = 0.f, bl0 = 0.f, bl1 = 0.f, bl2 = 0.f, bl3 = 0.f;
    if (bid < 128) {
        int gidx = bid * 128 + tid;
        gb = gidx >> 9; gu = gidx & 511;
        c = c0[gb * 512 + gu];
        bl0 = b_lstm[gu];        bl1 = b_lstm[512 + gu];
        bl2 = b_lstm[1024 + gu]; bl3 = b_lstm[1536 + gu];
    }

    float* zp0 = &g_zpart[(size_t)ks * NB * G4 + col];   // + b*G4 per row

    for (int t = 0; t < NT; t++) {
        // stage h slice (written by gates last step; L2-coherent, bypass L1)
#pragma unroll
        for (int i = 0; i < 2; i++) {
            float4 v = __ldcg(reinterpret_cast<const float4*>(
                &g_h[k0 * 32 + tid * 4 + i * 512]));
            *reinterpret_cast<float4*>(&hs[tid * 4 + i * 512]) = v;
        }
        __syncthreads();

        // packed-f32x2 GEMM: acc[b-pair] += h[b-pair] * (w,w)
        unsigned long long accp[16] = {};
#pragma unroll 4
        for (int k = 0; k < 32; k++) {
            unsigned long long wp;
            asm("mov.b64 %0, {%1, %1};" : "=l"(wp) : "f"(wreg[k]));
            const ulonglong2* hp = reinterpret_cast<const ulonglong2*>(&hs[k * 32]);
#pragma unroll
            for (int q = 0; q < 8; q++) {
                ulonglong2 h2 = hp[q];
                asm("fma.rn.f32x2 %0, %1, %2, %0;"
                    : "+l"(accp[q * 2 + 0]) : "l"(h2.x), "l"(wp));
                asm("fma.rn.f32x2 %0, %1, %2, %0;"
                    : "+l"(accp[q * 2 + 1]) : "l"(h2.y), "l"(wp));
            }
        }
        // unpack pairs -> coalesced STG.32 per b-row (lanes consecutive in col)
#pragma unroll
        for (int p = 0; p < 16; p++) {
            float lo, hi;
            asm("mov.b64 {%0, %1}, %2;" : "=f"(lo), "=f"(hi) : "l"(accp[p]));
            zp0[(size_t)(2 * p) * G4]     = lo;
            zp0[(size_t)(2 * p + 1) * G4] = hi;
        }

        gridbar(2 * t + 1);

        if (bid < 128) {
            const float* xw = g_xwx + (size_t)(t * 32 + gb) * G4;
            float zi = __ldg(xw + gu)        + bl0;
            float zf = __ldg(xw + 512 + gu)  + bl1;
            float zg = __ldg(xw + 1024 + gu) + bl2;
            float zo = __ldg(xw + 1536 + gu) + bl3;
#pragma unroll
            for (int s = 0; s < 16; s++) {
                const float* zp = g_zpart + (size_t)(s * 32 + gb) * G4;
                zi += __ldcg(zp + gu);
                zf += __ldcg(zp + 512 + gu);
                zg += __ldcg(zp + 1024 + gu);
                zo += __ldcg(zp + 1536 + gu);
            }
            float ig = 1.f / (1.f + expf(-zi));
            float fg = 1.f / (1.f + expf(-zf));
            float gg = tanhf(zg);
            float og = 1.f / (1.f + expf(-zo));
            c = fg * c + ig * gg;
            float h = og * tanhf(c);
            g_h[gu * 32 + gb] = h;
            g_hall[(size_t)(gb * 63 + t) * 512 + gu] = h;
            g_catb[(size_t)(gb * 63 + t) * 1024 + 512 + gu] = __float2bfloat16(h);
        }

        gridbar(2 * t + 2);
    }
}

// ---------------- batched attention: scores + softmax -------------------------
__global__ __launch_bounds__(256) void score_kernel() {
    int b = blockIdx.x, th = blockIdx.y;
    int t0 = th * 32;
    int nt = th ? 31 : 32;
    __shared__ float se[64 * 65];
    __shared__ float sh[32 * 65];
    int tid = threadIdx.x;
    int tq = tid >> 5, lq = tid & 31;
    float a[4][2] = {};
    for (int kc = 0; kc < 8; kc++) {
        int kk0 = kc * 64;
        for (int i = tid; i < 64 * 64; i += 256) {
            int l = i >> 6, kk = i & 63;
            se[l * 65 + kk] = g_encproj[((size_t)b * 64 + l) * 512 + kk0 + kk];
        }
        for (int i = tid; i < 32 * 64; i += 256) {
            int tt = i >> 6, kk = i & 63;
            sh[tt * 65 + kk] = (tt < nt)
                ? g_hall[((size_t)(b * 63 + t0 + tt)) * 512 + kk0 + kk] : 0.f;
        }
        __syncthreads();
#pragma unroll 8
        for (int kk = 0; kk < 64; kk++) {
            float e0 = se[lq * 65 + kk];
            float e1 = se[(lq + 32) * 65 + kk];
#pragma unroll
            for (int ii = 0; ii < 4; ii++) {
                float hv = sh[(tq * 4 + ii) * 65 + kk];
                a[ii][0] += hv * e0;
                a[ii][1] += hv * e1;
            }
        }
        __syncthreads();
    }
#pragma unroll
    for (int ii = 0; ii < 4; ii++) {
        float m = fmaxf(a[ii][0], a[ii][1]);
        for (int off = 16; off; off >>= 1)
            m = fmaxf(m, __shfl_xor_sync(0xffffffffu, m, off));
        float e0 = expf(a[ii][0] - m), e1 = expf(a[ii][1] - m);
        float s = e0 + e1;
        for (int off = 16; off; off >>= 1)
            s += __shfl_xor_sync(0xffffffffu, s, off);
        int tt = tq * 4 + ii;
        if (tt < nt) {
            size_t base = (size_t)(b * 63 + t0 + tt) * 64;
            g_attnw[base + lq]      = e0 / s;
            g_attnw[base + lq + 32] = e1 / s;
        }
    }
}

// ---------------- batched ctx = attn @ enc, write bf16 directly ---------------
__global__ __launch_bounds__(512) void ctx_kernel(const float* __restrict__ enc) {
    int b = blockIdx.x, tg = blockIdx.y;
    int u = threadIdx.x;
    __shared__ float aw[9 * 64];
    for (int i = u; i < 9 * 64; i += 512) {
        int tt = i >> 6, l = i & 63;
        aw[i] = g_attnw[(size_t)(b * 63 + tg * 9 + tt) * 64 + l];
    }
    __syncthreads();
    float acc[9] = {};
#pragma unroll 4
    for (int l = 0; l < 64; l++) {
        float e = __ldg(&enc[((size_t)b * 64 + l) * 512 + u]);
#pragma unroll
        for (int tt = 0; tt < 9; tt++) acc[tt] += aw[tt * 64 + l] * e;
    }
#pragma unroll
    for (int tt = 0; tt < 9; tt++)
        g_catb[(size_t)(b * 63 + tg * 9 + tt) * 1024 + u] = __float2bfloat16(acc[tt]);
}

// ---------------- output FC v2: 128x256 block, 64x64 warp tiles ---------------
#define FC_ALD 40
#define FC_BLD 280
#define FC_SMEM 56832

__global__ __launch_bounds__(256) void fc_wmma_kernel(const float* __restrict__ b_fc,
                                                      float* __restrict__ out) {
    extern __shared__ char smem[];
    __nv_bfloat16* Asp = reinterpret_cast<__nv_bfloat16*>(smem);
    __nv_bfloat16* Bsp = reinterpret_cast<__nv_bfloat16*>(smem + 20480);
    float* rowacc = reinterpret_cast<float*>(smem + 56320);
    float* stageb = reinterpret_cast<float*>(smem);

    int tid = threadIdx.x;
    int n0 = blockIdx.x * 256, m0 = blockIdx.y * 128;
    int w = tid >> 5, lane = tid & 31;
    int warpM = w >> 2, warpN = w & 3;           // 2 x 4 warps, warp tile 64x64

    uint32_t asu = smem_u32(Asp);
    uint32_t bsu = smem_u32(Bsp);

    auto load_tile = [&](int buf, int ktc) {
        uint32_t ab = asu + (uint32_t)buf * 10240;
        uint32_t bb = bsu + (uint32_t)buf * 17920;
#pragma unroll
        for (int rep = 0; rep < 2; rep++) {
            int o = tid + rep * 256;
            int row = o >> 2, c8 = (o & 3) * 8;
            cp16(ab + (uint32_t)(row * FC_ALD + c8) * 2,
                 g_catb + ((size_t)(m0 + row) * 1024 + ktc * 32 + c8));
        }
#pragma unroll
        for (int rep = 0; rep < 4; rep++) {
            int o = tid + rep * 256;
            int row2 = o >> 5, seg = (o & 31) * 8;
            cp16(bb + (uint32_t)(row2 * FC_BLD + seg) * 2,
                 g_wfcb + ((size_t)(ktc * 32 + row2) * 32000 + n0 + seg));
        }
        CP_COMMIT();
    };

    wmma::fragment<wmma::accumulator, 16, 16, 16, float> acc[4][4];
#pragma unroll
    for (int mi = 0; mi < 4; mi++)
#pragma unroll
        for (int ni = 0; ni < 4; ni++) wmma::fill_fragment(acc[mi][ni], 0.f);

    load_tile(0, 0);

    for (int kt = 0; kt < 32; kt++) {
        int cur = kt & 1;
        if (kt + 1 < 32) {
            load_tile(cur ^ 1, kt + 1);
            CP_WAIT(1);
        } else {
            CP_WAIT(0);
        }
        __syncthreads();

        const __nv_bfloat16* Ab = Asp + cur * 5120;
        const __nv_bfloat16* Bb = Bsp + cur * 8960;
#pragma unroll
        for (int kf = 0; kf < 2; kf++) {
            wmma::fragment<wmma::matrix_a, 16, 16, 16, __nv_bfloat16, wmma::row_major> af[4];
            wmma::fragment<wmma::matrix_b, 16, 16, 16, __nv_bfloat16, wmma::row_major> bfr[4];
#pragma unroll
            for (int mi = 0; mi < 4; mi++)
                wmma::load_matrix_sync(af[mi], Ab + (warpM * 64 + mi * 16) * FC_ALD + kf * 16, FC_ALD);
#pragma unroll
            for (int ni = 0; ni < 4; ni++)
                wmma::load_matrix_sync(bfr[ni], Bb + (kf * 16) * FC_BLD + warpN * 64 + ni * 16, FC_BLD);
#pragma unroll
            for (int mi = 0; mi < 4; mi++)
#pragma unroll
                for (int ni = 0; ni < 4; ni++)
                    wmma::mma_sync(acc[mi][ni], af[mi], bfr[ni], acc[mi][ni]);
        }
        __syncthreads();
    }

    // epilogue: stage in As[0] region, rowacc for exp sums
    if (tid < 128) rowacc[tid] = 0.f;
    __syncthreads();

    float* st = stageb + w * 256;
#pragma unroll
    for (int mi = 0; mi < 4; mi++) {
#pragma unroll
        for (int ni = 0; ni < 4; ni++) {
            wmma::store_matrix_sync(st, acc[mi][ni], 16, wmma::mem_row_major);
            __syncwarp();
            int r0 = m0 + warpM * 64 + mi * 16;
            int c0 = n0 + warpN * 64 + ni * 16;
#pragma unroll
            for (int j = 0; j < 8; j++) {
                int e = lane + j * 32;
                int rr = e >> 4, cc = e & 15;
                int r = r0 + rr;
                float val = tanhf(st[e] + __ldg(&b_fc[c0 + cc]));
                if (r < 2016)
                    out[(size_t)r * 32000 + c0 + cc] = val;
                // exp row-sum: |val| <= 1, no max-stabilization needed.
                float ex = __expf(val);
                ex += __shfl_xor_sync(0xffffffffu, ex, 8);
                ex += __shfl_xor_sync(0xffffffffu, ex, 4);
                ex += __shfl_xor_sync(0xffffffffu, ex, 2);
                ex += __shfl_xor_sync(0xffffffffu, ex, 1);
                if ((lane & 15) == 0)
                    atomicAdd(&rowacc[warpM * 64 + mi * 16 + rr], ex);
            }
            __syncwarp();
        }
    }
    __syncthreads();
    if (tid < 128) {
        int r = m0 + tid;
        if (r < 2016) atomicAdd(&g_rowsum[r], rowacc[tid]);
    }
}

// ---------------- subtract log(rowsum) ----------------------------------------
__global__ void sub_kernel(float* __restrict__ out) {
    int r = blockIdx.y;
    int v = (blockIdx.x * 256 + threadIdx.x) * 4;
    if (v < NV) {
        float lg = logf(g_rowsum[r]);
        float4* p = reinterpret_cast<float4*>(out + (size_t)r * NV + v);
        float4 x = *p;
        x.x -= lg; x.y -= lg; x.z -= lg; x.w -= lg;
        *p = x;
    }
}

// ---------------- launch ------------------------------------------------------
extern "C" void kernel_launch(void* const* d_in, const int* in_sizes, int n_in,
                              void* d_out, int out_size) {
    const int*   target = (const int*)d_in[0];
    const float* enc    = (const float*)d_in[1];
    const float* h0     = (const float*)d_in[2];
    const float* c0     = (const float*)d_in[3];
    const float* emb    = (const float*)d_in[4];
    const float* W_x    = (const float*)d_in[5];
    const float* W_h    = (const float*)d_in[6];
    const float* b_lstm = (const float*)d_in[7];
    const float* Wa     = (const float*)d_in[8];
    const float* W_fc   = (const float*)d_in[9];
    const float* b_fc   = (const float*)d_in[10];
    float* out = (float*)d_out;

    float *px, *pxwx, *pencproj;
    cudaGetSymbolAddress((void**)&px, g_x);
    cudaGetSymbolAddress((void**)&pxwx, g_xwx);
    cudaGetSymbolAddress((void**)&pencproj, g_encproj);

    cudaFuncSetAttribute(fc_wmma_kernel, cudaFuncAttributeMaxDynamicSharedMemorySize, FC_SMEM);

    // ordered so recur_kernel is the 4th launch (gets the ncu sample)
    gather_x_kernel<<<2016, 256>>>(target, emb);
    // xWx = g_x(2016x256) @ W_x(256x2048)
    sgemm128<<<dim3(32, 16), 256>>>(px, W_x, pxwx, 2016, 2048, 256);
    init_kernel<<<64, 256>>>(h0);
    // fused 63-step recurrence (persistent, grid-wide barriers)
    recur_kernel<<<RBLK, 128>>>(W_h, b_lstm, c0);

    // encproj = enc(2048x512) @ Wa(512x512)  (needed only by score)
    sgemm128<<<dim3(8, 16), 256>>>(enc, Wa, pencproj, 2048, 512, 512);
    score_kernel<<<dim3(32, 2), 256>>>();
    ctx_kernel<<<dim3(32, 7), 512>>>(enc);

    convert_wfc_kernel<<<4096, 256>>>(W_fc);
    // big FC with fused exp-rowsum, then log-softmax finalize
    fc_wmma_kernel<<<dim3(125, 16), 256, FC_SMEM>>>(b_fc, out);
    sub_kernel<<<dim3(32, 2016), 256>>>(out);
}